// round 10
// baseline (speedup 1.0000x reference)
#include <cuda_runtime.h>
#include <cstdint>

// HGN forward. Shapes fixed: U=I=100000, D=64, L=50, B=4096, T=100.
#define D 64
#define LSEQ 50
#define TPRED 100
#define PRE_BPB 4
#define BMAX 4096
#define SUBMAX 13

typedef unsigned long long u64;

__device__ float g_ubias[BMAX * D];    // u@fg_user_W + fub + fib
__device__ float g_ugu[BMAX * LSEQ];   // u@instance_gate_user

static __device__ __forceinline__ u64 pk(float a, float b) {
    u64 r;
    asm("mov.b64 %0, {%1, %2};" : "=l"(r) : "f"(a), "f"(b));
    return r;
}
static __device__ __forceinline__ void upk(u64 v, float& a, float& b) {
    asm("mov.b64 {%0, %1}, %2;" : "=f"(a), "=f"(b) : "l"(v));
}
static __device__ __forceinline__ u64 fma2(u64 a, u64 b, u64 c) {
    u64 r;
    asm("fma.rn.f32x2 %0, %1, %2, %3;" : "=l"(r) : "l"(a), "l"(b), "l"(c));
    return r;
}
static __device__ __forceinline__ u64 add2(u64 a, u64 b) {
    u64 r;
    asm("add.rn.f32x2 %0, %1, %2;" : "=l"(r) : "l"(a), "l"(b));
    return r;
}
static __device__ __forceinline__ float sigmoidf(float x) {
    return 1.0f / (1.0f + __expf(-x));
}
static __device__ __forceinline__ uint32_t smem_u32(const void* p) {
    uint32_t a;
    asm("{ .reg .u64 t; cvta.to.shared.u64 t, %1; cvt.u32.u64 %0, t; }" : "=r"(a) : "l"(p));
    return a;
}
static __device__ __forceinline__ void cp16(uint32_t dst, const void* src) {
    asm volatile("cp.async.cg.shared.global [%0], [%1], 16;" :: "r"(dst), "l"(src) : "memory");
}
#define CP_COMMIT() asm volatile("cp.async.commit_group;" ::: "memory")
#define CP_WAIT0()  asm volatile("cp.async.wait_group 0;" ::: "memory")

// ---------------------------------------------------------------------------
// Precompute: g_ubias[b][d] = u@fg_user_W + fub + fib ; g_ugu[b][l] = u@gu
// ---------------------------------------------------------------------------
__global__ __launch_bounds__(128) void hgn_pre(
    const int* __restrict__ user_ids, const float* __restrict__ user_tab,
    const float* __restrict__ fuW, const float* __restrict__ fub,
    const float* __restrict__ fib, const float* __restrict__ gu, int B)
{
    __shared__ __align__(16) float s_u[D];
    const int j = threadIdx.x;
    float wcol[D];
    float biasj = 0.0f;
    if (j < D) {
        #pragma unroll
        for (int k = 0; k < D; k++) wcol[k] = fuW[k * D + j];
        biasj = fub[j] + fib[j];
    } else if (j < D + LSEQ) {
        const int jj = j - D;
        #pragma unroll
        for (int k = 0; k < D; k++) wcol[k] = gu[k * LSEQ + jj];
    }
    const int b0 = blockIdx.x * PRE_BPB;
    for (int bb = 0; bb < PRE_BPB; bb++) {
        const int b = b0 + bb;
        if (b >= B) break;
        if (j < D) s_u[j] = user_tab[(size_t)user_ids[b] * D + j];
        __syncthreads();
        float acc = biasj;
        const float4* up = (const float4*)s_u;
        #pragma unroll
        for (int q = 0; q < D / 4; q++) {
            float4 r = up[q];
            acc += r.x * wcol[4*q] + r.y * wcol[4*q+1] + r.z * wcol[4*q+2] + r.w * wcol[4*q+3];
        }
        if (j < D)             g_ubias[b * D + j] = acc;
        else if (j < D + LSEQ) g_ugu[b * LSEQ + (j - D)] = acc;
        __syncthreads();
    }
}

// ---------------------------------------------------------------------------
// Main kernel: one batch per 128-thread block, 4 warps = 4 K-quarters.
// Lane owns column pair (d=lane, d=lane+32); packed f32x2 weights in regs.
// Instance score fused into the combine pass. Gated values overwrite s_item
// rows packed: gated(d) at s_item[l][2*(d&31) + (d>>5)].
// s_pp is reused post-GEMM as a cp.async W2 prefetch buffer (first 48 rows).
// ---------------------------------------------------------------------------
__global__ __launch_bounds__(128, 8) void hgn_main(
    const int* __restrict__ item_seq,
    const int* __restrict__ user_ids,
    const int* __restrict__ items_pred,
    const float* __restrict__ user_tab,
    const float* __restrict__ item_tab,
    const float* __restrict__ fiW,
    const float* __restrict__ gi,
    const float* __restrict__ W2,
    const float* __restrict__ b2,
    float* __restrict__ out,
    int B)
{
    __shared__ __align__(16) float s_item[LSEQ][D];     // items -> gated (packed, in place)
    __shared__ __align__(16) u64 s_pp[4][SUBMAX][32];   // partials; later W2 prefetch
    __shared__ __align__(16) u64 s_isump[4][32];        // per-warp packed item sums
    __shared__ __align__(16) float s_v[D];
    __shared__ __align__(16) float s_uop[2][D];         // union partials (l-halves)
    __shared__ float s_ssp[2];
    __shared__ float s_score[LSEQ];
    __shared__ int s_idx[TPRED];

    const int tid  = threadIdx.x;
    const int lane = tid & 31;
    const int w    = tid >> 5;       // warp = K-quarter
    const int b    = blockIdx.x;
    if (b >= B) return;

    // Packed weight quarter: colp[j] = (fiW[16w+j][lane], fiW[16w+j][lane+32])
    u64 colp[16];
    #pragma unroll
    for (int j = 0; j < 16; j++) {
        colp[j] = pk(fiW[(16 * w + j) * D + lane],
                     fiW[(16 * w + j) * D + lane + 32]);
    }
    const float gi_lo = gi[lane];
    const float gi_hi = gi[lane + 32];

    // --- gather item rows (16 threads share one seq index -> LDG bcast);
    //     stage prediction indices in the same phase ---
    #pragma unroll
    for (int i = 0; i < 7; i++) {
        const int idx = tid + 128 * i;
        if (idx < LSEQ * 16) {
            const int rl = idx >> 4, q = idx & 15;
            const int it = __ldg(&item_seq[(size_t)b * LSEQ + rl]);
            ((float4*)s_item[rl])[q] =
                ((const float4*)(item_tab + (size_t)it * D))[q];
        }
    }
    if (tid < TPRED) s_idx[tid] = items_pred[(size_t)b * TPRED + tid];
    const float biasA = g_ubias[b * D + lane];
    const float biasB = g_ubias[b * D + lane + 32];
    const float uemb  = (tid < D) ? user_tab[(size_t)user_ids[b] * D + tid] : 0.0f;
    __syncthreads();

    // --- gating GEMM + fused combine/instance-score, 4 row subtiles ---
    const int SUB0[5] = {0, 13, 26, 38, 50};
    u64 isum2 = pk(0.f, 0.f);
    #pragma unroll
    for (int s = 0; s < 4; s++) {
        const int l0 = SUB0[s], l1 = SUB0[s + 1];
        int l = l0;
        for (; l + 1 < l1; l += 2) {
            u64 a0 = pk(0.f, 0.f), a1 = pk(0.f, 0.f);
            u64 c0 = pk(0.f, 0.f), c1 = pk(0.f, 0.f);
            const float4* r0 = (const float4*)&s_item[l][16 * w];
            const float4* r1 = (const float4*)&s_item[l + 1][16 * w];
            #pragma unroll
            for (int q = 0; q < 4; q++) {
                const float4 x = r0[q];
                a0 = fma2(pk(x.x, x.x), colp[4*q+0], a0);
                a1 = fma2(pk(x.y, x.y), colp[4*q+1], a1);
                a0 = fma2(pk(x.z, x.z), colp[4*q+2], a0);
                a1 = fma2(pk(x.w, x.w), colp[4*q+3], a1);
                const float4 y = r1[q];
                c0 = fma2(pk(y.x, y.x), colp[4*q+0], c0);
                c1 = fma2(pk(y.y, y.y), colp[4*q+1], c1);
                c0 = fma2(pk(y.z, y.z), colp[4*q+2], c0);
                c1 = fma2(pk(y.w, y.w), colp[4*q+3], c1);
            }
            s_pp[w][l - l0][lane]     = add2(a0, a1);
            s_pp[w][l + 1 - l0][lane] = add2(c0, c1);
        }
        if (l < l1) {
            u64 a0 = pk(0.f, 0.f), a1 = pk(0.f, 0.f);
            const float4* r0 = (const float4*)&s_item[l][16 * w];
            #pragma unroll
            for (int q = 0; q < 4; q++) {
                const float4 x = r0[q];
                a0 = fma2(pk(x.x, x.x), colp[4*q+0], a0);
                a1 = fma2(pk(x.y, x.y), colp[4*q+1], a1);
                a0 = fma2(pk(x.z, x.z), colp[4*q+2], a0);
                a1 = fma2(pk(x.w, x.w), colp[4*q+3], a1);
            }
            s_pp[w][l - l0][lane] = add2(a0, a1);
        }
        __syncthreads();
        // combine + gate + instance score, rows strided over warps.
        // (No __syncwarp needed: same-warp LDS->STS to the same row execute
        //  in program order; rows are warp-exclusive.)
        for (int lc = l0 + w; lc < l1; lc += 4) {
            const float ug = g_ugu[b * LSEQ + lc];
            const float itA = s_item[lc][lane];
            const float itB = s_item[lc][lane + 32];
            const u64 p = add2(add2(s_pp[0][lc - l0][lane], s_pp[1][lc - l0][lane]),
                               add2(s_pp[2][lc - l0][lane], s_pp[3][lc - l0][lane]));
            float pA, pB;
            upk(p, pA, pB);
            const float gA = itA * sigmoidf(pA + biasA);
            const float gB = itB * sigmoidf(pB + biasB);
            isum2 = add2(isum2, pk(itA, itB));
            float sp = gA * gi_lo + gB * gi_hi;
            sp += __shfl_xor_sync(0xffffffffu, sp, 16);
            sp += __shfl_xor_sync(0xffffffffu, sp, 8);
            sp += __shfl_xor_sync(0xffffffffu, sp, 4);
            sp += __shfl_xor_sync(0xffffffffu, sp, 2);
            sp += __shfl_xor_sync(0xffffffffu, sp, 1);
            if (lane == 0) s_score[lc] = sigmoidf(sp + ug);
            ((float2*)s_item[lc])[lane] = make_float2(gA, gB);
        }
        __syncthreads();
    }
    s_isump[w][lane] = isum2;

    // --- W2 prefetch (rows t=0..47 -> dead s_pp buffer) via cp.async,
    //     overlapped with the union partial phase ---
    float* s_w2 = (float*)s_pp;                 // [48][64] floats = 12.3KB <= 13.3KB
    const uint32_t s_w2_u32 = smem_u32(s_pp);
    #pragma unroll
    for (int i = 0; i < 6; i++) {
        const int idx = tid + 128 * i;          // 768 x 16B transfers
        const int row = idx >> 4, q = idx & 15;
        const int it = s_idx[row];
        cp16(s_w2_u32 + (uint32_t)idx * 16, W2 + (size_t)it * D + q * 4);
    }
    CP_COMMIT();

    // --- union partials: all 128 threads, two l-halves of 25 ---
    {
        const int h = tid >> 6, dloc = tid & 63;
        const int j = dloc & 31, half = dloc >> 5;
        const int l0 = h * 25;
        float ssum = 0.0f, uo = 0.0f;
        #pragma unroll 5
        for (int l = l0; l < l0 + 25; l++) {
            const float sc = s_score[l];
            ssum += sc;
            uo += s_item[l][2 * j + half] * sc;
        }
        s_uop[h][dloc] = uo;
        if (dloc == 0) s_ssp[h] = ssum;
    }
    CP_WAIT0();
    __syncthreads();

    // --- v (64 threads) ---
    if (tid < D) {
        const int j = tid & 31, half = tid >> 5;
        const u64 is4 = add2(add2(s_isump[0][j], s_isump[1][j]),
                             add2(s_isump[2][j], s_isump[3][j]));
        float isA, isB;
        upk(is4, isA, isB);
        const float ssum = s_ssp[0] + s_ssp[1];
        s_v[tid] = uemb + (half ? isB : isA)
                 + (s_uop[0][tid] + s_uop[1][tid]) / ssum;
    }
    __syncthreads();

    // --- scoring: iters 0-2 from smem prefetch; 3-6 from global, paired ---
    {
        const int g4 = lane >> 3;
        const int gl = lane & 7;
        const float4 va = *(const float4*)&s_v[gl * 8];
        const float4 vb = *(const float4*)&s_v[gl * 8 + 4];
        float* outp = out + (size_t)b * TPRED;

        #pragma unroll
        for (int i = 0; i < 3; i++) {
            const int t = w * 4 + g4 + 16 * i;          // t < 48
            const float* rp = s_w2 + t * D + gl * 8;
            const float4 a = *(const float4*)rp;
            const float4 c = *(const float4*)(rp + 4);
            const float bb2 = b2[s_idx[t]];
            float p = a.x * va.x + a.y * va.y + a.z * va.z + a.w * va.w
                    + c.x * vb.x + c.y * vb.y + c.z * vb.z + c.w * vb.w;
            p += __shfl_xor_sync(0xffffffffu, p, 1);
            p += __shfl_xor_sync(0xffffffffu, p, 2);
            p += __shfl_xor_sync(0xffffffffu, p, 4);
            if (gl == 0) outp[t] = p + bb2;
        }
        #pragma unroll
        for (int ip = 0; ip < 2; ip++) {                // pairs (3,4) and (5,6)
            const int t0 = w * 4 + g4 + 16 * (3 + 2 * ip);
            const int t1 = t0 + 16;
            const int tt1 = (t1 < TPRED) ? t1 : 0;
            const int it0 = s_idx[t0];
            const int it1 = s_idx[tt1];
            const float4* rp0 = (const float4*)(W2 + (size_t)it0 * D);
            const float4* rp1 = (const float4*)(W2 + (size_t)it1 * D);
            const float4 a0 = rp0[gl * 2], c0 = rp0[gl * 2 + 1];
            const float4 a1 = rp1[gl * 2], c1 = rp1[gl * 2 + 1];
            const float b20 = b2[it0];
            const float b21 = b2[it1];
            float p0 = a0.x * va.x + a0.y * va.y + a0.z * va.z + a0.w * va.w
                     + c0.x * vb.x + c0.y * vb.y + c0.z * vb.z + c0.w * vb.w;
            float p1 = a1.x * va.x + a1.y * va.y + a1.z * va.z + a1.w * va.w
                     + c1.x * vb.x + c1.y * vb.y + c1.z * vb.z + c1.w * vb.w;
            p0 += __shfl_xor_sync(0xffffffffu, p0, 1);
            p1 += __shfl_xor_sync(0xffffffffu, p1, 1);
            p0 += __shfl_xor_sync(0xffffffffu, p0, 2);
            p1 += __shfl_xor_sync(0xffffffffu, p1, 2);
            p0 += __shfl_xor_sync(0xffffffffu, p0, 4);
            p1 += __shfl_xor_sync(0xffffffffu, p1, 4);
            if (gl == 0) {
                outp[t0] = p0 + b20;
                if (t1 < TPRED) outp[t1] = p1 + b21;
            }
        }
    }
}

// ---------------------------------------------------------------------------
// Harness entry. Inputs (metadata order):
//  0 item_seq[B,L] i32   1 user_ids[B] i32      2 items_to_predict[B,T] i32
//  3 user_emb[U,D] f32   4 item_emb[I,D] f32
//  5 fg_item_W[D,D]      6 fg_item_b[D]         7 fg_user_W[D,D]   8 fg_user_b[D]
//  9 instance_gate_item[D,1]  10 instance_gate_user[D,L]
// 11 W2_table[I,D]      12 b2_table[I,1]
// Output: res[B,T] f32
// ---------------------------------------------------------------------------
extern "C" void kernel_launch(void* const* d_in, const int* in_sizes, int n_in,
                              void* d_out, int out_size)
{
    const int*   item_seq   = (const int*)d_in[0];
    const int*   user_ids   = (const int*)d_in[1];
    const int*   items_pred = (const int*)d_in[2];
    const float* user_tab   = (const float*)d_in[3];
    const float* item_tab   = (const float*)d_in[4];
    const float* fiW        = (const float*)d_in[5];
    const float* fib        = (const float*)d_in[6];
    const float* fuW        = (const float*)d_in[7];
    const float* fub        = (const float*)d_in[8];
    const float* gi         = (const float*)d_in[9];
    const float* gu         = (const float*)d_in[10];
    const float* W2         = (const float*)d_in[11];
    const float* b2         = (const float*)d_in[12];
    float*       out        = (float*)d_out;

    const int B = in_sizes[1];

    const int pre_grid = (B + PRE_BPB - 1) / PRE_BPB;

    hgn_pre<<<pre_grid, 128>>>(user_ids, user_tab, fuW, fub, fib, gu, B);
    hgn_main<<<B, 128>>>(item_seq, user_ids, items_pred,
                         user_tab, item_tab, fiW, gi, W2, b2, out, B);
}

// round 11
// speedup vs baseline: 1.0698x; 1.0698x over previous
#include <cuda_runtime.h>
#include <cstdint>

// HGN forward. Shapes fixed: U=I=100000, D=64, L=50, B=4096, T=100.
#define D 64
#define LSEQ 50
#define TPRED 100
#define PRE_BPB 4
#define BMAX 4096
#define SUBMAX 13

typedef unsigned long long u64;

__device__ float g_ubias[BMAX * D];    // u@fg_user_W + fub + fib
__device__ float g_ugu[BMAX * LSEQ];   // u@instance_gate_user

static __device__ __forceinline__ u64 pk(float a, float b) {
    u64 r;
    asm("mov.b64 %0, {%1, %2};" : "=l"(r) : "f"(a), "f"(b));
    return r;
}
static __device__ __forceinline__ void upk(u64 v, float& a, float& b) {
    asm("mov.b64 {%0, %1}, %2;" : "=f"(a), "=f"(b) : "l"(v));
}
static __device__ __forceinline__ u64 fma2(u64 a, u64 b, u64 c) {
    u64 r;
    asm("fma.rn.f32x2 %0, %1, %2, %3;" : "=l"(r) : "l"(a), "l"(b), "l"(c));
    return r;
}
static __device__ __forceinline__ u64 add2(u64 a, u64 b) {
    u64 r;
    asm("add.rn.f32x2 %0, %1, %2;" : "=l"(r) : "l"(a), "l"(b));
    return r;
}
static __device__ __forceinline__ float sigmoidf(float x) {
    return 1.0f / (1.0f + __expf(-x));
}
static __device__ __forceinline__ uint32_t smem_u32(const void* p) {
    uint32_t a;
    asm("{ .reg .u64 t; cvta.to.shared.u64 t, %1; cvt.u32.u64 %0, t; }" : "=r"(a) : "l"(p));
    return a;
}
static __device__ __forceinline__ void cp16(uint32_t dst, const void* src) {
    asm volatile("cp.async.cg.shared.global [%0], [%1], 16;" :: "r"(dst), "l"(src) : "memory");
}
#define CP_COMMIT() asm volatile("cp.async.commit_group;" ::: "memory")
#define CP_WAIT0()  asm volatile("cp.async.wait_group 0;" ::: "memory")

// ---------------------------------------------------------------------------
// Precompute: g_ubias[b][d] = u@fg_user_W + fub + fib ; g_ugu[b][l] = u@gu
// ---------------------------------------------------------------------------
__global__ __launch_bounds__(128) void hgn_pre(
    const int* __restrict__ user_ids, const float* __restrict__ user_tab,
    const float* __restrict__ fuW, const float* __restrict__ fub,
    const float* __restrict__ fib, const float* __restrict__ gu, int B)
{
    __shared__ __align__(16) float s_u[D];
    const int j = threadIdx.x;
    float wcol[D];
    float biasj = 0.0f;
    if (j < D) {
        #pragma unroll
        for (int k = 0; k < D; k++) wcol[k] = fuW[k * D + j];
        biasj = fub[j] + fib[j];
    } else if (j < D + LSEQ) {
        const int jj = j - D;
        #pragma unroll
        for (int k = 0; k < D; k++) wcol[k] = gu[k * LSEQ + jj];
    }
    const int b0 = blockIdx.x * PRE_BPB;
    for (int bb = 0; bb < PRE_BPB; bb++) {
        const int b = b0 + bb;
        if (b >= B) break;
        if (j < D) s_u[j] = user_tab[(size_t)user_ids[b] * D + j];
        __syncthreads();
        float acc = biasj;
        const float4* up = (const float4*)s_u;
        #pragma unroll
        for (int q = 0; q < D / 4; q++) {
            float4 r = up[q];
            acc += r.x * wcol[4*q] + r.y * wcol[4*q+1] + r.z * wcol[4*q+2] + r.w * wcol[4*q+3];
        }
        if (j < D)             g_ubias[b * D + j] = acc;
        else if (j < D + LSEQ) g_ugu[b * LSEQ + (j - D)] = acc;
        __syncthreads();
    }
}

// ---------------------------------------------------------------------------
// Main kernel: one batch per 128-thread block, 4 warps = 4 K-quarters.
// Lane owns column pair (d=lane, d=lane+32); packed f32x2 weights in regs.
// Instance score fused into the combine pass. Gated values overwrite s_item
// rows packed: gated(d) at s_item[l][2*(d&31) + (d>>5)].
// s_pp is reused post-GEMM as a cp.async W2 prefetch buffer (rows 0..47).
// SMEM kept <= 28KB so 8 blocks/SM fit (R10 lesson: +520B cost a block).
// ---------------------------------------------------------------------------
__global__ __launch_bounds__(128, 8) void hgn_main(
    const int* __restrict__ item_seq,
    const int* __restrict__ user_ids,
    const int* __restrict__ items_pred,
    const float* __restrict__ user_tab,
    const float* __restrict__ item_tab,
    const float* __restrict__ fiW,
    const float* __restrict__ gi,
    const float* __restrict__ W2,
    const float* __restrict__ b2,
    float* __restrict__ out,
    int B)
{
    __shared__ __align__(16) float s_item[LSEQ][D];     // items -> gated (packed, in place)
    __shared__ __align__(16) u64 s_pp[4][SUBMAX][32];   // partials; later W2 prefetch
    __shared__ __align__(16) u64 s_isump[4][32];        // per-warp packed item sums
    __shared__ __align__(16) float s_v[D];
    __shared__ float s_score[LSEQ];
    __shared__ int s_idx[TPRED];

    const int tid  = threadIdx.x;
    const int lane = tid & 31;
    const int w    = tid >> 5;       // warp = K-quarter
    const int b    = blockIdx.x;
    if (b >= B) return;

    // Packed weight quarter: colp[j] = (fiW[16w+j][lane], fiW[16w+j][lane+32])
    u64 colp[16];
    #pragma unroll
    for (int j = 0; j < 16; j++) {
        colp[j] = pk(fiW[(16 * w + j) * D + lane],
                     fiW[(16 * w + j) * D + lane + 32]);
    }
    const float gi_lo = gi[lane];
    const float gi_hi = gi[lane + 32];

    // --- gather item rows (16 threads share one seq index -> LDG bcast);
    //     stage prediction indices in the same phase ---
    #pragma unroll
    for (int i = 0; i < 7; i++) {
        const int idx = tid + 128 * i;
        if (idx < LSEQ * 16) {
            const int rl = idx >> 4, q = idx & 15;
            const int it = __ldg(&item_seq[(size_t)b * LSEQ + rl]);
            ((float4*)s_item[rl])[q] =
                ((const float4*)(item_tab + (size_t)it * D))[q];
        }
    }
    if (tid < TPRED) s_idx[tid] = items_pred[(size_t)b * TPRED + tid];
    const float biasA = g_ubias[b * D + lane];
    const float biasB = g_ubias[b * D + lane + 32];
    const float uemb  = (tid < D) ? user_tab[(size_t)user_ids[b] * D + tid] : 0.0f;
    __syncthreads();

    // --- gating GEMM + fused combine/instance-score, 4 row subtiles ---
    const int SUB0[5] = {0, 13, 26, 38, 50};
    u64 isum2 = pk(0.f, 0.f);
    #pragma unroll
    for (int s = 0; s < 4; s++) {
        const int l0 = SUB0[s], l1 = SUB0[s + 1];
        int l = l0;
        for (; l + 1 < l1; l += 2) {
            u64 a0 = pk(0.f, 0.f), a1 = pk(0.f, 0.f);
            u64 c0 = pk(0.f, 0.f), c1 = pk(0.f, 0.f);
            const float4* r0 = (const float4*)&s_item[l][16 * w];
            const float4* r1 = (const float4*)&s_item[l + 1][16 * w];
            #pragma unroll
            for (int q = 0; q < 4; q++) {
                const float4 x = r0[q];
                a0 = fma2(pk(x.x, x.x), colp[4*q+0], a0);
                a1 = fma2(pk(x.y, x.y), colp[4*q+1], a1);
                a0 = fma2(pk(x.z, x.z), colp[4*q+2], a0);
                a1 = fma2(pk(x.w, x.w), colp[4*q+3], a1);
                const float4 y = r1[q];
                c0 = fma2(pk(y.x, y.x), colp[4*q+0], c0);
                c1 = fma2(pk(y.y, y.y), colp[4*q+1], c1);
                c0 = fma2(pk(y.z, y.z), colp[4*q+2], c0);
                c1 = fma2(pk(y.w, y.w), colp[4*q+3], c1);
            }
            s_pp[w][l - l0][lane]     = add2(a0, a1);
            s_pp[w][l + 1 - l0][lane] = add2(c0, c1);
        }
        if (l < l1) {
            u64 a0 = pk(0.f, 0.f), a1 = pk(0.f, 0.f);
            const float4* r0 = (const float4*)&s_item[l][16 * w];
            #pragma unroll
            for (int q = 0; q < 4; q++) {
                const float4 x = r0[q];
                a0 = fma2(pk(x.x, x.x), colp[4*q+0], a0);
                a1 = fma2(pk(x.y, x.y), colp[4*q+1], a1);
                a0 = fma2(pk(x.z, x.z), colp[4*q+2], a0);
                a1 = fma2(pk(x.w, x.w), colp[4*q+3], a1);
            }
            s_pp[w][l - l0][lane] = add2(a0, a1);
        }
        __syncthreads();
        // combine + gate + instance score, rows strided over warps.
        // (No __syncwarp: same-warp LDS->STS to the same row are program-order;
        //  rows are warp-exclusive within this phase.)
        for (int lc = l0 + w; lc < l1; lc += 4) {
            const float ug = g_ugu[b * LSEQ + lc];
            const float itA = s_item[lc][lane];
            const float itB = s_item[lc][lane + 32];
            const u64 p = add2(add2(s_pp[0][lc - l0][lane], s_pp[1][lc - l0][lane]),
                               add2(s_pp[2][lc - l0][lane], s_pp[3][lc - l0][lane]));
            float pA, pB;
            upk(p, pA, pB);
            const float gA = itA * sigmoidf(pA + biasA);
            const float gB = itB * sigmoidf(pB + biasB);
            isum2 = add2(isum2, pk(itA, itB));
            float sp = gA * gi_lo + gB * gi_hi;
            sp += __shfl_xor_sync(0xffffffffu, sp, 16);
            sp += __shfl_xor_sync(0xffffffffu, sp, 8);
            sp += __shfl_xor_sync(0xffffffffu, sp, 4);
            sp += __shfl_xor_sync(0xffffffffu, sp, 2);
            sp += __shfl_xor_sync(0xffffffffu, sp, 1);
            if (lane == 0) s_score[lc] = sigmoidf(sp + ug);
            ((float2*)s_item[lc])[lane] = make_float2(gA, gB);
        }
        __syncthreads();
    }
    s_isump[w][lane] = isum2;

    // --- W2 prefetch (rows t=0..47 -> dead s_pp buffer) via cp.async,
    //     overlapped with the union phase below ---
    float* s_w2 = (float*)s_pp;                 // [48][64] floats = 12.3KB
    const uint32_t s_w2_u32 = smem_u32(s_pp);
    #pragma unroll
    for (int i = 0; i < 6; i++) {
        const int idx = tid + 128 * i;          // 768 x 16B transfers
        const int row = idx >> 4, q = idx & 15;
        const int it = s_idx[row];
        cp16(s_w2_u32 + (uint32_t)idx * 16, W2 + (size_t)it * D + q * 4);
    }
    CP_COMMIT();

    // --- union + v (64 threads; warps 2-3 idle but covering cp.async) ---
    if (tid < D) {
        const int j = tid & 31, half = tid >> 5;
        float ssum = 0.0f, uo = 0.0f;
        #pragma unroll 5
        for (int l = 0; l < LSEQ; l++) {
            const float sc = s_score[l];
            ssum += sc;
            uo += s_item[l][2 * j + half] * sc;
        }
        const u64 is4 = add2(add2(s_isump[0][j], s_isump[1][j]),
                             add2(s_isump[2][j], s_isump[3][j]));
        float isA, isB;
        upk(is4, isA, isB);
        s_v[tid] = uemb + (half ? isB : isA) + uo / ssum;
    }
    CP_WAIT0();
    __syncthreads();

    // --- scoring: iters 0-2 from smem prefetch; 3-6 from global, paired ---
    {
        const int g4 = lane >> 3;
        const int gl = lane & 7;
        const float4 va = *(const float4*)&s_v[gl * 8];
        const float4 vb = *(const float4*)&s_v[gl * 8 + 4];
        float* outp = out + (size_t)b * TPRED;

        #pragma unroll
        for (int i = 0; i < 3; i++) {
            const int t = w * 4 + g4 + 16 * i;          // t < 48
            const float* rp = s_w2 + t * D + gl * 8;
            const float4 a = *(const float4*)rp;
            const float4 c = *(const float4*)(rp + 4);
            const float bb2 = b2[s_idx[t]];
            float p = a.x * va.x + a.y * va.y + a.z * va.z + a.w * va.w
                    + c.x * vb.x + c.y * vb.y + c.z * vb.z + c.w * vb.w;
            p += __shfl_xor_sync(0xffffffffu, p, 1);
            p += __shfl_xor_sync(0xffffffffu, p, 2);
            p += __shfl_xor_sync(0xffffffffu, p, 4);
            if (gl == 0) outp[t] = p + bb2;
        }
        #pragma unroll
        for (int ip = 0; ip < 2; ip++) {                // pairs (3,4) and (5,6)
            const int t0 = w * 4 + g4 + 16 * (3 + 2 * ip);
            const int t1 = t0 + 16;
            const int tt1 = (t1 < TPRED) ? t1 : 0;
            const int it0 = s_idx[t0];
            const int it1 = s_idx[tt1];
            const float4* rp0 = (const float4*)(W2 + (size_t)it0 * D);
            const float4* rp1 = (const float4*)(W2 + (size_t)it1 * D);
            const float4 a0 = rp0[gl * 2], c0 = rp0[gl * 2 + 1];
            const float4 a1 = rp1[gl * 2], c1 = rp1[gl * 2 + 1];
            const float b20 = b2[it0];
            const float b21 = b2[it1];
            float p0 = a0.x * va.x + a0.y * va.y + a0.z * va.z + a0.w * va.w
                     + c0.x * vb.x + c0.y * vb.y + c0.z * vb.z + c0.w * vb.w;
            float p1 = a1.x * va.x + a1.y * va.y + a1.z * va.z + a1.w * va.w
                     + c1.x * vb.x + c1.y * vb.y + c1.z * vb.z + c1.w * vb.w;
            p0 += __shfl_xor_sync(0xffffffffu, p0, 1);
            p1 += __shfl_xor_sync(0xffffffffu, p1, 1);
            p0 += __shfl_xor_sync(0xffffffffu, p0, 2);
            p1 += __shfl_xor_sync(0xffffffffu, p1, 2);
            p0 += __shfl_xor_sync(0xffffffffu, p0, 4);
            p1 += __shfl_xor_sync(0xffffffffu, p1, 4);
            if (gl == 0) {
                outp[t0] = p0 + b20;
                if (t1 < TPRED) outp[t1] = p1 + b21;
            }
        }
    }
}

// ---------------------------------------------------------------------------
// Harness entry. Inputs (metadata order):
//  0 item_seq[B,L] i32   1 user_ids[B] i32      2 items_to_predict[B,T] i32
//  3 user_emb[U,D] f32   4 item_emb[I,D] f32
//  5 fg_item_W[D,D]      6 fg_item_b[D]         7 fg_user_W[D,D]   8 fg_user_b[D]
//  9 instance_gate_item[D,1]  10 instance_gate_user[D,L]
// 11 W2_table[I,D]      12 b2_table[I,1]
// Output: res[B,T] f32
// ---------------------------------------------------------------------------
extern "C" void kernel_launch(void* const* d_in, const int* in_sizes, int n_in,
                              void* d_out, int out_size)
{
    const int*   item_seq   = (const int*)d_in[0];
    const int*   user_ids   = (const int*)d_in[1];
    const int*   items_pred = (const int*)d_in[2];
    const float* user_tab   = (const float*)d_in[3];
    const float* item_tab   = (const float*)d_in[4];
    const float* fiW        = (const float*)d_in[5];
    const float* fib        = (const float*)d_in[6];
    const float* fuW        = (const float*)d_in[7];
    const float* fub        = (const float*)d_in[8];
    const float* gi         = (const float*)d_in[9];
    const float* gu         = (const float*)d_in[10];
    const float* W2         = (const float*)d_in[11];
    const float* b2         = (const float*)d_in[12];
    float*       out        = (float*)d_out;

    const int B = in_sizes[1];

    const int pre_grid = (B + PRE_BPB - 1) / PRE_BPB;

    hgn_pre<<<pre_grid, 128>>>(user_ids, user_tab, fuW, fub, fib, gu, B);
    hgn_main<<<B, 128>>>(item_seq, user_ids, items_pred,
                         user_tab, item_tab, fiW, gi, W2, b2, out, B);
}